// round 6
// baseline (speedup 1.0000x reference)
#include <cuda_runtime.h>

#define T_TOK 2048
#define SDIM  1024
#define EDIM  1024
#define HID   150
#define MAXW  10

#define TMM   16              // tokens per MLP block
#define MLPT  640             // MLP threads (20 warps)
#define KPAD  1032            // As row stride in FLOATS (1024 data + 8 pad)
#define HPAD  158             // h row stride in floats (8B-aligned, bank-spread)

__device__ float g_attns[T_TOK];

// packed 2xfp32 FMA: acc = w * a + acc (lanewise on .b64)
#define FMA2(acc, w_, a_) \
    asm volatile("fma.rn.f32x2 %0, %1, %2, %0;" : "+l"(acc) : "l"(w_), "l"(a_))

__device__ __forceinline__ float pairsum(unsigned long long v) {
    float lo, hi;
    asm("mov.b64 {%0,%1}, %2;" : "=f"(lo), "=f"(hi) : "l"(v));
    return lo + hi;
}

// ---------------------------------------------------------------------------
// Kernel 1: fused 3-layer MLP -> per-token scalar score.
// grid=128 x 640 threads. Thread = (hidden j = tid>>2, token quarter q=tid&3
// -> tokens {q, q+4, q+8, q+12}). Full-K accumulation, no reductions.
// Weight stream read through a DEPTH-4 rolling register buffer => 4 loads in
// flight per warp => L2 latency / 4 exposed => SMSP flips to issue-bound.
// ---------------------------------------------------------------------------
__global__ __launch_bounds__(MLPT) void mlp_kernel(
    const float* __restrict__ states,
    const float* __restrict__ w1, const float* __restrict__ b1,
    const float* __restrict__ w2, const float* __restrict__ b2,
    const float* __restrict__ w3, const float* __restrict__ b3)
{
    __shared__ __align__(16) float As[TMM][KPAD];    // ~66 KB
    __shared__ __align__(16) float h1s[TMM][HPAD];
    __shared__ __align__(16) float h2s[TMM][HPAD];

    const int tid = threadIdx.x;
    const int t0  = blockIdx.x * TMM;

    // stage 16 token states (coalesced float4 loads)
    for (int idx = tid; idx < TMM * (SDIM / 4); idx += MLPT) {
        const int t = idx >> 8, k4 = idx & 255;
        const float4 v = ((const float4*)states)[(size_t)(t0 + t) * 256 + k4];
        *(float4*)&As[t][k4 * 4] = v;
    }
    __syncthreads();

    const int q  = tid & 3;
    const int jj = tid >> 2;            // 0..159 (>=150 are shadow threads)
    const int jc = min(jj, HID - 1);

    const float* A0 = As[q + 0];
    const float* A1 = As[q + 4];
    const float* A2 = As[q + 8];
    const float* A3 = As[q + 12];

    // ---------------- layer 1: h1 = relu(states @ w1^T + b1) ----------------
    {
        const ulonglong2* wr = (const ulonglong2*)(w1 + (size_t)jc * SDIM);

        ulonglong2 wbuf[4];
        #pragma unroll
        for (int i = 0; i < 4; i++) wbuf[i] = wr[i];

        unsigned long long acc0 = 0, acc1 = 0, acc2 = 0, acc3 = 0;

        for (int base = 0; base < 256; base += 4) {
            #pragma unroll
            for (int s = 0; s < 4; s++) {
                const ulonglong2 cw = wbuf[s];
                const int nxt = base + 4 + s;
                if (nxt < 256) wbuf[s] = wr[nxt];   // keep 4 loads in flight
                const int k4 = base + s;
                const ulonglong2 a0 = *(const ulonglong2*)(A0 + 4 * k4);
                const ulonglong2 a1 = *(const ulonglong2*)(A1 + 4 * k4);
                const ulonglong2 a2 = *(const ulonglong2*)(A2 + 4 * k4);
                const ulonglong2 a3 = *(const ulonglong2*)(A3 + 4 * k4);
                FMA2(acc0, cw.x, a0.x); FMA2(acc0, cw.y, a0.y);
                FMA2(acc1, cw.x, a1.x); FMA2(acc1, cw.y, a1.y);
                FMA2(acc2, cw.x, a2.x); FMA2(acc2, cw.y, a2.y);
                FMA2(acc3, cw.x, a3.x); FMA2(acc3, cw.y, a3.y);
            }
        }
        if (jj < HID) {
            const float bb = b1[jj];
            h1s[q + 0 ][jj] = fmaxf(pairsum(acc0) + bb, 0.f);
            h1s[q + 4 ][jj] = fmaxf(pairsum(acc1) + bb, 0.f);
            h1s[q + 8 ][jj] = fmaxf(pairsum(acc2) + bb, 0.f);
            h1s[q + 12][jj] = fmaxf(pairsum(acc3) + bb, 0.f);
        }
    }
    __syncthreads();

    // ---------------- layer 2: h2 = relu(h1 @ w2^T + b2) --------------------
    {
        const unsigned long long* wr2 =
            (const unsigned long long*)(w2 + (size_t)jc * HID);  // 75 k-pairs
        const float* B0 = h1s[q + 0];
        const float* B1 = h1s[q + 4];
        const float* B2 = h1s[q + 8];
        const float* B3 = h1s[q + 12];

        unsigned long long wbuf[4];
        #pragma unroll
        for (int i = 0; i < 4; i++) wbuf[i] = wr2[i];

        unsigned long long acc0 = 0, acc1 = 0, acc2 = 0, acc3 = 0;

        for (int base = 0; base < 76; base += 4) {
            #pragma unroll
            for (int s = 0; s < 4; s++) {
                const int p = base + s;
                const unsigned long long wv = wbuf[s];
                const int nxt = base + 4 + s;
                if (nxt < 75) wbuf[s] = wr2[nxt];
                if (p < 75) {
                    const unsigned long long a0 = *(const unsigned long long*)(B0 + 2 * p);
                    const unsigned long long a1 = *(const unsigned long long*)(B1 + 2 * p);
                    const unsigned long long a2 = *(const unsigned long long*)(B2 + 2 * p);
                    const unsigned long long a3 = *(const unsigned long long*)(B3 + 2 * p);
                    FMA2(acc0, wv, a0);
                    FMA2(acc1, wv, a1);
                    FMA2(acc2, wv, a2);
                    FMA2(acc3, wv, a3);
                }
            }
        }
        if (jj < HID) {
            const float bb = b2[jj];
            h2s[q + 0 ][jj] = fmaxf(pairsum(acc0) + bb, 0.f);
            h2s[q + 4 ][jj] = fmaxf(pairsum(acc1) + bb, 0.f);
            h2s[q + 8 ][jj] = fmaxf(pairsum(acc2) + bb, 0.f);
            h2s[q + 12][jj] = fmaxf(pairsum(acc3) + bb, 0.f);
        }
    }
    __syncthreads();

    // ---------------- layer 3: attns = h2 @ w3^T + b3 -----------------------
    {
        const int wrp  = tid >> 5;
        const int lane = tid & 31;
        if (wrp < TMM) {                 // warp w handles token w
            float acc = 0.f;
            #pragma unroll
            for (int i = 0; i < 5; ++i) {
                const int kk = lane + 32 * i;
                if (kk < HID) acc += w3[kk] * h2s[wrp][kk];
            }
            #pragma unroll
            for (int off = 16; off; off >>= 1)
                acc += __shfl_xor_sync(0xffffffffu, acc, off);
            if (lane == 0) g_attns[t0 + wrp] = acc + b3[0];
        }
    }
}

// ---------------------------------------------------------------------------
// Kernel 2: span assembly (unchanged — at the HBM write floor for 4 rounds)
// ---------------------------------------------------------------------------
__global__ __launch_bounds__(256) void assemble_kernel(
    const float* __restrict__ embeds,
    const float* __restrict__ states,
    float* __restrict__ out)
{
    const int r    = blockIdx.x;
    const int tid  = threadIdx.x;
    const int nmax = min(MAXW, T_TOK - r);

    __shared__ __align__(16) float se[MAXW][EDIM];   // 40 KB
    __shared__ float ws[MAXW];
    __shared__ float invden[MAXW];

    {
        unsigned smem_addr = (unsigned)__cvta_generic_to_shared(&se[0][tid * 4]);
        const float4* src = (const float4*)embeds + (size_t)r * 256 + tid;
        #pragma unroll
        for (int i = 0; i < MAXW; i++) {
            if (i < nmax) {
                asm volatile("cp.async.cg.shared.global [%0], [%1], 16;\n"
                             :: "r"(smem_addr + i * (EDIM * 4)), "l"(src + i * 256));
            }
        }
        asm volatile("cp.async.commit_group;\n" ::: "memory");
    }

    if (tid == 0) {
        float a[MAXW];
        float m = -1e30f;
        for (int i = 0; i < nmax; i++) {
            a[i] = g_attns[r + i];
            m = fmaxf(m, a[i]);
        }
        float den = 0.f;
        for (int i = 0; i < nmax; i++) {
            float e = __expf(a[i] - m);
            ws[i] = e;
            den += e;
            invden[i] = 1.0f / den;
        }
    }
    asm volatile("cp.async.wait_group 0;\n" ::: "memory");
    __syncthreads();

    const float4* st4  = (const float4*)states;
    float4*       out4 = (float4*)out;

    const float4 s0 = st4[r * 256 + tid];
    float4 num = make_float4(0.f, 0.f, 0.f, 0.f);

    #pragma unroll
    for (int i = 0; i < MAXW; i++) {
        if (i < nmax) {
            const float  wv = ws[i];
            const float4 e  = ((const float4*)se[i])[tid];
            num.x += wv * e.x; num.y += wv * e.y;
            num.z += wv * e.z; num.w += wv * e.w;

            // section offset for width n=i+1: (n-1)*2049 - n(n-1)/2
            const int row  = i * (T_TOK + 1) - ((i + 1) * i) / 2 + r;
            const int base = row * 768;                // 3072 floats / 4

            const float4 send = st4[(r + i) * 256 + tid];
            const float  id   = invden[i];
            __stcs(&out4[base + tid],       s0);
            __stcs(&out4[base + 256 + tid], send);
            __stcs(&out4[base + 512 + tid],
                   make_float4(num.x * id, num.y * id, num.z * id, num.w * id));
        }
    }
}

// ---------------------------------------------------------------------------
extern "C" void kernel_launch(void* const* d_in, const int* in_sizes, int n_in,
                              void* d_out, int out_size) {
    const float* embeds = (const float*)d_in[0];
    const float* states = (const float*)d_in[1];
    const float* w1     = (const float*)d_in[2];
    const float* b1     = (const float*)d_in[3];
    const float* w2     = (const float*)d_in[4];
    const float* b2     = (const float*)d_in[5];
    const float* w3     = (const float*)d_in[6];
    const float* b3     = (const float*)d_in[7];
    float* out = (float*)d_out;

    mlp_kernel<<<T_TOK / TMM, MLPT>>>(states, w1, b1, w2, b2, w3, b3);
    assemble_kernel<<<T_TOK, 256>>>(embeds, states, out);
}

// round 9
// speedup vs baseline: 1.2654x; 1.2654x over previous
#include <cuda_runtime.h>

#define T_TOK 2048
#define SDIM  1024
#define EDIM  1024
#define HID   150
#define MAXW  10

#define TMM    16             // tokens per MLP block
#define MLPT   320            // MLP threads (10 warps)
#define KPAD   1032           // As row stride (floats)
#define HPAD   158            // h row stride (floats)
#define WROW   76             // w1 tile row stride (floats)
#define W2ROW  156            // w2 tile row stride (floats)
#define KC     64             // K-chunk (floats)
#define CHUNKS 16             // 1024 / 64
#define WTILE  (160 * WROW)   // floats per w1 buffer (12160)

// static smem layout (floats):
//   As   [16*1032] = 16512
//   wt   [2*WTILE] = 24320   (aliased by w2 tile: max offset 23549)
//   h1s  [16*158]  =  2528
//   h2s  [16*158]  =  2528
#define SMEM_FLOATS (TMM*KPAD + 2*WTILE + 2*TMM*HPAD)   // 45888 -> 183.5 KB

__device__ float g_attns[T_TOK];

typedef unsigned long long ull;

#define FMA2(acc, w_, a_) \
    asm volatile("fma.rn.f32x2 %0, %1, %2, %0;" : "+l"(acc) : "l"(w_), "l"(a_))

#define CP16(dst_s, src_g) \
    asm volatile("cp.async.cg.shared.global [%0], [%1], 16;\n" :: "r"(dst_s), "l"(src_g))
#define CP4(dst_s, src_g) \
    asm volatile("cp.async.ca.shared.global [%0], [%1], 4;\n" :: "r"(dst_s), "l"(src_g))

__device__ __forceinline__ float pairsum(ull v) {
    float lo, hi;
    asm("mov.b64 {%0,%1}, %2;" : "=f"(lo), "=f"(hi) : "l"(v));
    return lo + hi;
}

// ---------------------------------------------------------------------------
// Kernel 1: fused 3-layer MLP -> per-token scalar score.
// grid=128 x 320 threads. Thread = (hidden pair jp = tid>>2, token quarter
// q = tid&3 -> tokens {q,q+4,q+8,q+12}). Full-K accumulation, no reductions.
// Weights cp.async-staged into SMEM (coalesced LDG) and read via broadcast
// LDS (1 wavefront/inst) -> L1tex wavefronts drop below the FMA2 floor.
// ---------------------------------------------------------------------------
__global__ __launch_bounds__(MLPT) void mlp_kernel(
    const float* __restrict__ states,
    const float* __restrict__ w1, const float* __restrict__ b1,
    const float* __restrict__ w2, const float* __restrict__ b2,
    const float* __restrict__ w3, const float* __restrict__ b3)
{
    __shared__ __align__(16) float sm[SMEM_FLOATS];
    float* As  = sm;                    // [16][KPAD]
    float* wt  = As + TMM * KPAD;       // [2][WTILE]  (later aliased by w2)
    float* h1s = wt + 2 * WTILE;        // [16][HPAD]
    float* h2s = h1s + TMM * HPAD;      // [16][HPAD]

    const int tid = threadIdx.x;
    const int t0  = blockIdx.x * TMM;

    const unsigned wt_s = (unsigned)__cvta_generic_to_shared(wt);

    // ---- stage w1 chunk 0 (coalesced cp.async; even/odd row interleave) ----
    for (int u = tid; u < HID * 16; u += MLPT) {     // rows 0..149 only
        const int j = u >> 4, seg = u & 15;
        const int rm = (j >> 1) + (j & 1) * 80;
        CP16(wt_s + (unsigned)(rm * WROW + seg * 4) * 4,
             w1 + (size_t)j * SDIM + seg * 4);
    }
    asm volatile("cp.async.commit_group;\n" ::: "memory");

    // ---- stage 16 token states (coalesced float4 STS) ----
    for (int idx = tid; idx < TMM * (SDIM / 4); idx += MLPT) {
        const int t = idx >> 8, k4 = idx & 255;
        const float4 v = ((const float4*)states)[(size_t)(t0 + t) * 256 + k4];
        *(float4*)&As[t * KPAD + k4 * 4] = v;
    }

    const int q  = tid & 3;
    const int jp = tid >> 2;            // 0..79
    const int j0 = 2 * jp;              // even hidden unit; j0+1 = odd
    const int re = min(jp, 74);         // smem row of even j (clamp shadows)
    const int ro = 80 + min(jp, 74);    // smem row of odd j

    const float* A0 = As + (q + 0)  * KPAD;
    const float* A1 = As + (q + 4)  * KPAD;
    const float* A2 = As + (q + 8)  * KPAD;
    const float* A3 = As + (q + 12) * KPAD;

    // ---------------- layer 1: h1 = relu(states @ w1^T + b1) ----------------
    ull ae0 = 0, ae1 = 0, ae2 = 0, ae3 = 0;   // even-j accs (4 tokens)
    ull ao0 = 0, ao1 = 0, ao2 = 0, ao3 = 0;   // odd-j accs

    for (int c = 0; c < CHUNKS; ++c) {
        if (c + 1 < CHUNKS) {
            const int nb = (c + 1) & 1;
            for (int u = tid; u < HID * 16; u += MLPT) {
                const int j = u >> 4, seg = u & 15;
                const int rm = (j >> 1) + (j & 1) * 80;
                CP16(wt_s + (unsigned)(nb * WTILE + rm * WROW + seg * 4) * 4,
                     w1 + (size_t)j * SDIM + (c + 1) * KC + seg * 4);
            }
            asm volatile("cp.async.commit_group;\n" ::: "memory");
            asm volatile("cp.async.wait_group 1;\n" ::: "memory");
        } else {
            asm volatile("cp.async.wait_group 0;\n" ::: "memory");
        }
        __syncthreads();

        const float* we = wt + (c & 1) * WTILE + re * WROW;
        const float* wo = wt + (c & 1) * WTILE + ro * WROW;
        const int kb = c * KC;

        #pragma unroll
        for (int k4 = 0; k4 < 16; ++k4) {
            const ulonglong2 w_e = *(const ulonglong2*)(we + k4 * 4);
            const ulonglong2 w_o = *(const ulonglong2*)(wo + k4 * 4);
            const ulonglong2 a0 = *(const ulonglong2*)(A0 + kb + k4 * 4);
            const ulonglong2 a1 = *(const ulonglong2*)(A1 + kb + k4 * 4);
            const ulonglong2 a2 = *(const ulonglong2*)(A2 + kb + k4 * 4);
            const ulonglong2 a3 = *(const ulonglong2*)(A3 + kb + k4 * 4);
            FMA2(ae0, w_e.x, a0.x); FMA2(ae0, w_e.y, a0.y);
            FMA2(ae1, w_e.x, a1.x); FMA2(ae1, w_e.y, a1.y);
            FMA2(ae2, w_e.x, a2.x); FMA2(ae2, w_e.y, a2.y);
            FMA2(ae3, w_e.x, a3.x); FMA2(ae3, w_e.y, a3.y);
            FMA2(ao0, w_o.x, a0.x); FMA2(ao0, w_o.y, a0.y);
            FMA2(ao1, w_o.x, a1.x); FMA2(ao1, w_o.y, a1.y);
            FMA2(ao2, w_o.x, a2.x); FMA2(ao2, w_o.y, a2.y);
            FMA2(ao3, w_o.x, a3.x); FMA2(ao3, w_o.y, a3.y);
        }
        __syncthreads();
    }

    // ---- stage w2 into the wt region (coalesced 4B cp.async), overlapped
    //      with the h1 epilogue ----
    for (int u = tid; u < HID * HID; u += MLPT) {
        const int j = u / HID, s = u - j * HID;
        const int rm = (j >> 1) + (j & 1) * 76;
        CP4(wt_s + (unsigned)(rm * W2ROW + s) * 4, w2 + (size_t)j * HID + s);
    }
    asm volatile("cp.async.commit_group;\n" ::: "memory");

    if (j0 < HID) {
        const float be = b1[j0], bo = b1[j0 + 1];
        h1s[(q + 0)  * HPAD + j0]     = fmaxf(pairsum(ae0) + be, 0.f);
        h1s[(q + 4)  * HPAD + j0]     = fmaxf(pairsum(ae1) + be, 0.f);
        h1s[(q + 8)  * HPAD + j0]     = fmaxf(pairsum(ae2) + be, 0.f);
        h1s[(q + 12) * HPAD + j0]     = fmaxf(pairsum(ae3) + be, 0.f);
        h1s[(q + 0)  * HPAD + j0 + 1] = fmaxf(pairsum(ao0) + bo, 0.f);
        h1s[(q + 4)  * HPAD + j0 + 1] = fmaxf(pairsum(ao1) + bo, 0.f);
        h1s[(q + 8)  * HPAD + j0 + 1] = fmaxf(pairsum(ao2) + bo, 0.f);
        h1s[(q + 12) * HPAD + j0 + 1] = fmaxf(pairsum(ao3) + bo, 0.f);
    }
    asm volatile("cp.async.wait_group 0;\n" ::: "memory");
    __syncthreads();

    // ---------------- layer 2: h2 = relu(h1 @ w2^T + b2) --------------------
    {
        const int jpc = min(jp, HID / 2 - 1);       // clamp shadow pairs
        const float* we2 = wt + jpc * W2ROW;        // even row = jpc
        const float* wo2 = wt + (76 + jpc) * W2ROW; // odd row
        const float* B0 = h1s + (q + 0)  * HPAD;
        const float* B1 = h1s + (q + 4)  * HPAD;
        const float* B2 = h1s + (q + 8)  * HPAD;
        const float* B3 = h1s + (q + 12) * HPAD;

        ull e0 = 0, e1 = 0, e2 = 0, e3 = 0;
        ull o0 = 0, o1 = 0, o2 = 0, o3 = 0;

        #pragma unroll 5
        for (int p = 0; p < HID / 2; ++p) {         // 75 k-pairs
            const ull w_e = *(const ull*)(we2 + 2 * p);
            const ull w_o = *(const ull*)(wo2 + 2 * p);
            const ull a0 = *(const ull*)(B0 + 2 * p);
            const ull a1 = *(const ull*)(B1 + 2 * p);
            const ull a2 = *(const ull*)(B2 + 2 * p);
            const ull a3 = *(const ull*)(B3 + 2 * p);
            FMA2(e0, w_e, a0); FMA2(e1, w_e, a1);
            FMA2(e2, w_e, a2); FMA2(e3, w_e, a3);
            FMA2(o0, w_o, a0); FMA2(o1, w_o, a1);
            FMA2(o2, w_o, a2); FMA2(o3, w_o, a3);
        }
        if (j0 < HID) {
            const float be = b2[j0], bo = b2[j0 + 1];
            h2s[(q + 0)  * HPAD + j0]     = fmaxf(pairsum(e0) + be, 0.f);
            h2s[(q + 4)  * HPAD + j0]     = fmaxf(pairsum(e1) + be, 0.f);
            h2s[(q + 8)  * HPAD + j0]     = fmaxf(pairsum(e2) + be, 0.f);
            h2s[(q + 12) * HPAD + j0]     = fmaxf(pairsum(e3) + be, 0.f);
            h2s[(q + 0)  * HPAD + j0 + 1] = fmaxf(pairsum(o0) + bo, 0.f);
            h2s[(q + 4)  * HPAD + j0 + 1] = fmaxf(pairsum(o1) + bo, 0.f);
            h2s[(q + 8)  * HPAD + j0 + 1] = fmaxf(pairsum(o2) + bo, 0.f);
            h2s[(q + 12) * HPAD + j0 + 1] = fmaxf(pairsum(o3) + bo, 0.f);
        }
    }
    __syncthreads();

    // ---------------- layer 3: attns = h2 @ w3^T + b3 -----------------------
    {
        const int wrp  = tid >> 5;
        const int lane = tid & 31;
        for (int t = wrp; t < TMM; t += MLPT / 32) {
            float acc = 0.f;
            #pragma unroll
            for (int i = 0; i < 5; ++i) {
                const int kk = lane + 32 * i;
                if (kk < HID) acc += w3[kk] * h2s[t * HPAD + kk];
            }
            #pragma unroll
            for (int off = 16; off; off >>= 1)
                acc += __shfl_xor_sync(0xffffffffu, acc, off);
            if (lane == 0) g_attns[t0 + t] = acc + b3[0];
        }
    }
}

// ---------------------------------------------------------------------------
// Kernel 2: span assembly (unchanged — pinned at the HBM write floor)
// ---------------------------------------------------------------------------
__global__ __launch_bounds__(256) void assemble_kernel(
    const float* __restrict__ embeds,
    const float* __restrict__ states,
    float* __restrict__ out)
{
    const int r    = blockIdx.x;
    const int tid  = threadIdx.x;
    const int nmax = min(MAXW, T_TOK - r);

    __shared__ __align__(16) float se[MAXW][EDIM];   // 40 KB
    __shared__ float ws[MAXW];
    __shared__ float invden[MAXW];

    {
        unsigned smem_addr = (unsigned)__cvta_generic_to_shared(&se[0][tid * 4]);
        const float4* src = (const float4*)embeds + (size_t)r * 256 + tid;
        #pragma unroll
        for (int i = 0; i < MAXW; i++) {
            if (i < nmax) {
                asm volatile("cp.async.cg.shared.global [%0], [%1], 16;\n"
                             :: "r"(smem_addr + i * (EDIM * 4)), "l"(src + i * 256));
            }
        }
        asm volatile("cp.async.commit_group;\n" ::: "memory");
    }

    if (tid == 0) {
        float a[MAXW];
        float m = -1e30f;
        for (int i = 0; i < nmax; i++) {
            a[i] = g_attns[r + i];
            m = fmaxf(m, a[i]);
        }
        float den = 0.f;
        for (int i = 0; i < nmax; i++) {
            float e = __expf(a[i] - m);
            ws[i] = e;
            den += e;
            invden[i] = 1.0f / den;
        }
    }
    asm volatile("cp.async.wait_group 0;\n" ::: "memory");
    __syncthreads();

    const float4* st4  = (const float4*)states;
    float4*       out4 = (float4*)out;

    const float4 s0 = st4[r * 256 + tid];
    float4 num = make_float4(0.f, 0.f, 0.f, 0.f);

    #pragma unroll
    for (int i = 0; i < MAXW; i++) {
        if (i < nmax) {
            const float  wv = ws[i];
            const float4 e  = ((const float4*)se[i])[tid];
            num.x += wv * e.x; num.y += wv * e.y;
            num.z += wv * e.z; num.w += wv * e.w;

            // section offset for width n=i+1: (n-1)*2049 - n(n-1)/2
            const int row  = i * (T_TOK + 1) - ((i + 1) * i) / 2 + r;
            const int base = row * 768;                // 3072 floats / 4

            const float4 send = st4[(r + i) * 256 + tid];
            const float  id   = invden[i];
            __stcs(&out4[base + tid],       s0);
            __stcs(&out4[base + 256 + tid], send);
            __stcs(&out4[base + 512 + tid],
                   make_float4(num.x * id, num.y * id, num.z * id, num.w * id));
        }
    }
}

// ---------------------------------------------------------------------------
extern "C" void kernel_launch(void* const* d_in, const int* in_sizes, int n_in,
                              void* d_out, int out_size) {
    const float* embeds = (const float*)d_in[0];
    const float* states = (const float*)d_in[1];
    const float* w1     = (const float*)d_in[2];
    const float* b1     = (const float*)d_in[3];
    const float* w2     = (const float*)d_in[4];
    const float* b2     = (const float*)d_in[5];
    const float* w3     = (const float*)d_in[6];
    const float* b3     = (const float*)d_in[7];
    float* out = (float*)d_out;

    mlp_kernel<<<T_TOK / TMM, MLPT>>>(states, w1, b1, w2, b2, w3, b3);
    assemble_kernel<<<T_TOK, 256>>>(embeds, states, out);
}

// round 10
// speedup vs baseline: 1.2882x; 1.0180x over previous
#include <cuda_runtime.h>

#define T_TOK 2048
#define SDIM  1024
#define EDIM  1024
#define HID   150
#define MAXW  10

#define TMM    16             // tokens per MLP block
#define MLPT   640            // MLP threads (20 warps = 5/SMSP)
#define KPAD   1032           // As row stride (floats)
#define HPAD   158            // h row stride (floats)
#define WROW   88             // w1 tile row stride (floats; bank-spread for kh split)
#define W2ROW  156            // w2 tile row stride (floats)
#define KC     64             // K-chunk (floats)
#define CHUNKS 16             // 1024 / 64
#define WTILE  (160 * WROW)   // floats per w1 buffer (14080)

// static smem (floats): As 16512 + wt 2*14080 + h1s 2528 + h2s 2528 = 49728
// -> 198.9 KB (sm_103a limit 227 KB), 1 CTA/SM
#define SMEM_FLOATS (TMM*KPAD + 2*WTILE + 2*TMM*HPAD)

__device__ float g_attns[T_TOK];

typedef unsigned long long ull;

#define FMA2(acc, w_, a_) \
    asm volatile("fma.rn.f32x2 %0, %1, %2, %0;" : "+l"(acc) : "l"(w_), "l"(a_))

#define CP16(dst_s, src_g) \
    asm volatile("cp.async.cg.shared.global [%0], [%1], 16;\n" :: "r"(dst_s), "l"(src_g))
#define CP8(dst_s, src_g) \
    asm volatile("cp.async.ca.shared.global [%0], [%1], 8;\n" :: "r"(dst_s), "l"(src_g))

__device__ __forceinline__ float pairsum(ull v) {
    float lo, hi;
    asm("mov.b64 {%0,%1}, %2;" : "=f"(lo), "=f"(hi) : "l"(v));
    return lo + hi;
}

// ---------------------------------------------------------------------------
// Kernel 1: fused 3-layer MLP -> per-token scalar score.
// grid=128 x 640. Layer 1: thread = (j-pair jp=tid>>3, k-parity kh=(tid>>2)&1,
// token quarter q=tid&3). Each thread accumulates its k4-parity class of K;
// partials summed in a combine pass. 5 warps/SMSP hide LDS/barrier stalls.
// Weights cp.async-staged (coalesced) and consumed via conflict-free LDS.
// ---------------------------------------------------------------------------
__global__ __launch_bounds__(MLPT) void mlp_kernel(
    const float* __restrict__ states,
    const float* __restrict__ w1, const float* __restrict__ b1,
    const float* __restrict__ w2, const float* __restrict__ b2,
    const float* __restrict__ w3, const float* __restrict__ b3)
{
    __shared__ __align__(16) float sm[SMEM_FLOATS];
    float* As  = sm;                    // [16][KPAD]
    float* wt  = As + TMM * KPAD;       // [2][WTILE] (later aliased by w2)
    float* h1s = wt + 2 * WTILE;        // [16][HPAD] (kh=0 partials -> final h1)
    float* h2s = h1s + TMM * HPAD;      // [16][HPAD] (kh=1 partials -> later h2)

    const int tid = threadIdx.x;
    const int t0  = blockIdx.x * TMM;

    const unsigned wt_s = (unsigned)__cvta_generic_to_shared(wt);

    // ---- stage w1 chunk 0 (coalesced cp.async; even/odd row interleave) ----
    for (int u = tid; u < HID * 16; u += MLPT) {
        const int j = u >> 4, seg = u & 15;
        const int rm = (j >> 1) + (j & 1) * 80;
        CP16(wt_s + (unsigned)(rm * WROW + seg * 4) * 4,
             w1 + (size_t)j * SDIM + seg * 4);
    }
    asm volatile("cp.async.commit_group;\n" ::: "memory");

    // ---- stage 16 token states ----
    for (int idx = tid; idx < TMM * (SDIM / 4); idx += MLPT) {
        const int t = idx >> 8, k4 = idx & 255;
        const float4 v = ((const float4*)states)[(size_t)(t0 + t) * 256 + k4];
        *(float4*)&As[t * KPAD + k4 * 4] = v;
    }

    const int q  = tid & 3;
    const int kh = (tid >> 2) & 1;      // k-parity
    const int jp = tid >> 3;            // 0..79 (75..79 shadow)
    const int j0 = 2 * jp;
    const int re = min(jp, 74);         // even-row index in tile
    const int ro = 80 + re;             // odd-row index

    const float* A0 = As + (q + 0)  * KPAD;
    const float* A1 = As + (q + 4)  * KPAD;
    const float* A2 = As + (q + 8)  * KPAD;
    const float* A3 = As + (q + 12) * KPAD;

    // ---------------- layer 1: partial dot over k4 ≡ kh (mod 2) -------------
    ull ae0 = 0, ae1 = 0, ae2 = 0, ae3 = 0;
    ull ao0 = 0, ao1 = 0, ao2 = 0, ao3 = 0;

    for (int c = 0; c < CHUNKS; ++c) {
        if (c + 1 < CHUNKS) {
            const int nb = (c + 1) & 1;
            for (int u = tid; u < HID * 16; u += MLPT) {
                const int j = u >> 4, seg = u & 15;
                const int rm = (j >> 1) + (j & 1) * 80;
                CP16(wt_s + (unsigned)(nb * WTILE + rm * WROW + seg * 4) * 4,
                     w1 + (size_t)j * SDIM + (c + 1) * KC + seg * 4);
            }
            asm volatile("cp.async.commit_group;\n" ::: "memory");
            asm volatile("cp.async.wait_group 1;\n" ::: "memory");
        } else {
            asm volatile("cp.async.wait_group 0;\n" ::: "memory");
        }
        __syncthreads();

        const float* wb = wt + (c & 1) * WTILE;
        const float* we = wb + re * WROW + kh * 4;
        const float* wo = wb + ro * WROW + kh * 4;
        const float* B0 = A0 + c * KC + kh * 4;
        const float* B1 = A1 + c * KC + kh * 4;
        const float* B2 = A2 + c * KC + kh * 4;
        const float* B3 = A3 + c * KC + kh * 4;

        #pragma unroll
        for (int i = 0; i < 8; ++i) {   // this thread's 8 parity k4-groups
            const int o = i * 8;
            const ulonglong2 w_e = *(const ulonglong2*)(we + o);
            const ulonglong2 w_o = *(const ulonglong2*)(wo + o);
            const ulonglong2 a0 = *(const ulonglong2*)(B0 + o);
            const ulonglong2 a1 = *(const ulonglong2*)(B1 + o);
            const ulonglong2 a2 = *(const ulonglong2*)(B2 + o);
            const ulonglong2 a3 = *(const ulonglong2*)(B3 + o);
            FMA2(ae0, w_e.x, a0.x); FMA2(ae0, w_e.y, a0.y);
            FMA2(ae1, w_e.x, a1.x); FMA2(ae1, w_e.y, a1.y);
            FMA2(ae2, w_e.x, a2.x); FMA2(ae2, w_e.y, a2.y);
            FMA2(ae3, w_e.x, a3.x); FMA2(ae3, w_e.y, a3.y);
            FMA2(ao0, w_o.x, a0.x); FMA2(ao0, w_o.y, a0.y);
            FMA2(ao1, w_o.x, a1.x); FMA2(ao1, w_o.y, a1.y);
            FMA2(ao2, w_o.x, a2.x); FMA2(ao2, w_o.y, a2.y);
            FMA2(ao3, w_o.x, a3.x); FMA2(ao3, w_o.y, a3.y);
        }
        __syncthreads();
    }

    // ---- stage w2 (8B cp.async; rows are 600B so 8B-aligned) ----
    for (int u = tid; u < HID * (HID / 2); u += MLPT) {
        const int j = u / (HID / 2), s2 = u - j * (HID / 2);
        const int rm = (j >> 1) + (j & 1) * 76;
        CP8(wt_s + (unsigned)(rm * W2ROW + s2 * 2) * 4,
            w2 + (size_t)j * HID + s2 * 2);
    }
    asm volatile("cp.async.commit_group;\n" ::: "memory");

    // ---- write layer-1 partials (kh=0 -> h1s, kh=1 -> h2s) ----
    if (j0 < HID) {
        float* P = kh ? h2s : h1s;
        P[(q + 0)  * HPAD + j0]     = pairsum(ae0);
        P[(q + 4)  * HPAD + j0]     = pairsum(ae1);
        P[(q + 8)  * HPAD + j0]     = pairsum(ae2);
        P[(q + 12) * HPAD + j0]     = pairsum(ae3);
        P[(q + 0)  * HPAD + j0 + 1] = pairsum(ao0);
        P[(q + 4)  * HPAD + j0 + 1] = pairsum(ao1);
        P[(q + 8)  * HPAD + j0 + 1] = pairsum(ao2);
        P[(q + 12) * HPAD + j0 + 1] = pairsum(ao3);
    }
    __syncthreads();

    // ---- combine partials: h1 = relu(p_even + p_odd + b1) ----
    for (int idx = tid; idx < TMM * 160; idx += MLPT) {
        const int t = idx / 160, j = idx - t * 160;
        if (j < HID)
            h1s[t * HPAD + j] = fmaxf(h1s[t * HPAD + j] + h2s[t * HPAD + j]
                                      + b1[j], 0.f);
    }
    asm volatile("cp.async.wait_group 0;\n" ::: "memory");
    __syncthreads();

    // ---------------- layer 2: h2 = relu(h1 @ w2^T + b2), one j/thread ------
    {
        const int j  = tid >> 2;                 // 0..159
        const int jc = min(j, HID - 1);
        const int rm = (jc >> 1) + (jc & 1) * 76;
        const float* wr = wt + rm * W2ROW;
        const float* B0 = h1s + (q + 0)  * HPAD;
        const float* B1 = h1s + (q + 4)  * HPAD;
        const float* B2 = h1s + (q + 8)  * HPAD;
        const float* B3 = h1s + (q + 12) * HPAD;

        ull c0 = 0, c1 = 0, c2 = 0, c3 = 0;
        #pragma unroll 5
        for (int p = 0; p < HID / 2; ++p) {
            const ull wv = *(const ull*)(wr + 2 * p);
            FMA2(c0, wv, *(const ull*)(B0 + 2 * p));
            FMA2(c1, wv, *(const ull*)(B1 + 2 * p));
            FMA2(c2, wv, *(const ull*)(B2 + 2 * p));
            FMA2(c3, wv, *(const ull*)(B3 + 2 * p));
        }
        __syncthreads();                         // h1 reads done before h2s reuse
        if (j < HID) {
            const float bb = b2[j];
            h2s[(q + 0)  * HPAD + j] = fmaxf(pairsum(c0) + bb, 0.f);
            h2s[(q + 4)  * HPAD + j] = fmaxf(pairsum(c1) + bb, 0.f);
            h2s[(q + 8)  * HPAD + j] = fmaxf(pairsum(c2) + bb, 0.f);
            h2s[(q + 12) * HPAD + j] = fmaxf(pairsum(c3) + bb, 0.f);
        }
    }
    __syncthreads();

    // ---------------- layer 3: attns = h2 @ w3^T + b3 -----------------------
    {
        const int wrp  = tid >> 5;
        const int lane = tid & 31;
        if (wrp < TMM) {
            float acc = 0.f;
            #pragma unroll
            for (int i = 0; i < 5; ++i) {
                const int kk = lane + 32 * i;
                if (kk < HID) acc += w3[kk] * h2s[wrp * HPAD + kk];
            }
            #pragma unroll
            for (int off = 16; off; off >>= 1)
                acc += __shfl_xor_sync(0xffffffffu, acc, off);
            if (lane == 0) g_attns[t0 + wrp] = acc + b3[0];
        }
    }
}

// ---------------------------------------------------------------------------
// Kernel 2: span assembly (unchanged — pinned at the HBM write floor)
// ---------------------------------------------------------------------------
__global__ __launch_bounds__(256) void assemble_kernel(
    const float* __restrict__ embeds,
    const float* __restrict__ states,
    float* __restrict__ out)
{
    const int r    = blockIdx.x;
    const int tid  = threadIdx.x;
    const int nmax = min(MAXW, T_TOK - r);

    __shared__ __align__(16) float se[MAXW][EDIM];
    __shared__ float ws[MAXW];
    __shared__ float invden[MAXW];

    {
        unsigned smem_addr = (unsigned)__cvta_generic_to_shared(&se[0][tid * 4]);
        const float4* src = (const float4*)embeds + (size_t)r * 256 + tid;
        #pragma unroll
        for (int i = 0; i < MAXW; i++) {
            if (i < nmax) {
                asm volatile("cp.async.cg.shared.global [%0], [%1], 16;\n"
                             :: "r"(smem_addr + i * (EDIM * 4)), "l"(src + i * 256));
            }
        }
        asm volatile("cp.async.commit_group;\n" ::: "memory");
    }

    if (tid == 0) {
        float a[MAXW];
        float m = -1e30f;
        for (int i = 0; i < nmax; i++) {
            a[i] = g_attns[r + i];
            m = fmaxf(m, a[i]);
        }
        float den = 0.f;
        for (int i = 0; i < nmax; i++) {
            float e = __expf(a[i] - m);
            ws[i] = e;
            den += e;
            invden[i] = 1.0f / den;
        }
    }
    asm volatile("cp.async.wait_group 0;\n" ::: "memory");
    __syncthreads();

    const float4* st4  = (const float4*)states;
    float4*       out4 = (float4*)out;

    const float4 s0 = st4[r * 256 + tid];
    float4 num = make_float4(0.f, 0.f, 0.f, 0.f);

    #pragma unroll
    for (int i = 0; i < MAXW; i++) {
        if (i < nmax) {
            const float  wv = ws[i];
            const float4 e  = ((const float4*)se[i])[tid];
            num.x += wv * e.x; num.y += wv * e.y;
            num.z += wv * e.z; num.w += wv * e.w;

            const int row  = i * (T_TOK + 1) - ((i + 1) * i) / 2 + r;
            const int base = row * 768;

            const float4 send = st4[(r + i) * 256 + tid];
            const float  id   = invden[i];
            __stcs(&out4[base + tid],       s0);
            __stcs(&out4[base + 256 + tid], send);
            __stcs(&out4[base + 512 + tid],
                   make_float4(num.x * id, num.y * id, num.z * id, num.w * id));
        }
    }
}

// ---------------------------------------------------------------------------
extern "C" void kernel_launch(void* const* d_in, const int* in_sizes, int n_in,
                              void* d_out, int out_size) {
    const float* embeds = (const float*)d_in[0];
    const float* states = (const float*)d_in[1];
    const float* w1     = (const float*)d_in[2];
    const float* b1     = (const float*)d_in[3];
    const float* w2     = (const float*)d_in[4];
    const float* b2     = (const float*)d_in[5];
    const float* w3     = (const float*)d_in[6];
    const float* b3     = (const float*)d_in[7];
    float* out = (float*)d_out;

    mlp_kernel<<<T_TOK / TMM, MLPT>>>(states, w1, b1, w2, b2, w3, b3);
    assemble_kernel<<<T_TOK, 256>>>(embeds, states, out);
}

// round 11
// speedup vs baseline: 1.3168x; 1.0222x over previous
#include <cuda_runtime.h>

#define T_TOK 2048
#define SDIM  1024
#define EDIM  1024
#define HID   150
#define MAXW  10

#define TMM    16             // tokens per MLP block
#define MLPT   640            // MLP threads (20 warps = 5/SMSP)
#define KPAD   1032           // As row stride (floats)
#define HPAD   158            // h row stride (floats)
#define WROW   88             // w1 tile row stride (floats)
#define W2ROW  156            // w2 tile row stride (floats)
#define KC     64             // K-chunk (floats)
#define CHUNKS 16             // 1024 / 64
#define WTILE  (160 * WROW)   // floats per w1 buffer (14080)

#define SMEM_FLOATS (TMM*KPAD + 2*WTILE + 2*TMM*HPAD)   // ~199 KB

__device__ float g_attns[T_TOK];

#define CP16(dst_s, src_g) \
    asm volatile("cp.async.cg.shared.global [%0], [%1], 16;\n" :: "r"(dst_s), "l"(src_g))
#define CP8(dst_s, src_g) \
    asm volatile("cp.async.ca.shared.global [%0], [%1], 8;\n" :: "r"(dst_s), "l"(src_g))

// ---------------------------------------------------------------------------
// Kernel 1: fused 3-layer MLP -> per-token scalar score.
// Identical structure to R10 (best: 94.3us) EXCEPT inner loops are plain
// fp32 FFMA (compiler-scheduled) instead of inline-asm fma.rn.f32x2 — A/B
// test of the FFMA2 lowering hypothesis.
// ---------------------------------------------------------------------------
__global__ __launch_bounds__(MLPT) void mlp_kernel(
    const float* __restrict__ states,
    const float* __restrict__ w1, const float* __restrict__ b1,
    const float* __restrict__ w2, const float* __restrict__ b2,
    const float* __restrict__ w3, const float* __restrict__ b3)
{
    __shared__ __align__(16) float sm[SMEM_FLOATS];
    float* As  = sm;                    // [16][KPAD]
    float* wt  = As + TMM * KPAD;       // [2][WTILE] (later aliased by w2)
    float* h1s = wt + 2 * WTILE;        // [16][HPAD] (kh=0 partials -> h1)
    float* h2s = h1s + TMM * HPAD;      // [16][HPAD] (kh=1 partials -> h2)

    const int tid = threadIdx.x;
    const int t0  = blockIdx.x * TMM;

    const unsigned wt_s = (unsigned)__cvta_generic_to_shared(wt);

    // ---- stage w1 chunk 0 (coalesced cp.async; even/odd row interleave) ----
    for (int u = tid; u < HID * 16; u += MLPT) {
        const int j = u >> 4, seg = u & 15;
        const int rm = (j >> 1) + (j & 1) * 80;
        CP16(wt_s + (unsigned)(rm * WROW + seg * 4) * 4,
             w1 + (size_t)j * SDIM + seg * 4);
    }
    asm volatile("cp.async.commit_group;\n" ::: "memory");

    // ---- stage 16 token states ----
    for (int idx = tid; idx < TMM * (SDIM / 4); idx += MLPT) {
        const int t = idx >> 8, k4 = idx & 255;
        const float4 v = ((const float4*)states)[(size_t)(t0 + t) * 256 + k4];
        *(float4*)&As[t * KPAD + k4 * 4] = v;
    }

    const int q  = tid & 3;
    const int kh = (tid >> 2) & 1;      // k-parity
    const int jp = tid >> 3;            // 0..79 (75..79 shadow)
    const int j0 = 2 * jp;
    const int re = min(jp, 74);
    const int ro = 80 + re;

    const float* A0 = As + (q + 0)  * KPAD;
    const float* A1 = As + (q + 4)  * KPAD;
    const float* A2 = As + (q + 8)  * KPAD;
    const float* A3 = As + (q + 12) * KPAD;

    // ---------------- layer 1: partial dot over k4 ≡ kh (mod 2) -------------
    float e0 = 0.f, e1 = 0.f, e2 = 0.f, e3 = 0.f;   // even-j, 4 tokens
    float o0 = 0.f, o1 = 0.f, o2 = 0.f, o3 = 0.f;   // odd-j,  4 tokens

    for (int c = 0; c < CHUNKS; ++c) {
        if (c + 1 < CHUNKS) {
            const int nb = (c + 1) & 1;
            for (int u = tid; u < HID * 16; u += MLPT) {
                const int j = u >> 4, seg = u & 15;
                const int rm = (j >> 1) + (j & 1) * 80;
                CP16(wt_s + (unsigned)(nb * WTILE + rm * WROW + seg * 4) * 4,
                     w1 + (size_t)j * SDIM + (c + 1) * KC + seg * 4);
            }
            asm volatile("cp.async.commit_group;\n" ::: "memory");
            asm volatile("cp.async.wait_group 1;\n" ::: "memory");
        } else {
            asm volatile("cp.async.wait_group 0;\n" ::: "memory");
        }
        __syncthreads();

        const float* wb = wt + (c & 1) * WTILE;
        const float* we = wb + re * WROW + kh * 4;
        const float* wo = wb + ro * WROW + kh * 4;
        const float* B0 = A0 + c * KC + kh * 4;
        const float* B1 = A1 + c * KC + kh * 4;
        const float* B2 = A2 + c * KC + kh * 4;
        const float* B3 = A3 + c * KC + kh * 4;

        #pragma unroll
        for (int i = 0; i < 8; ++i) {
            const int o = i * 8;
            const float4 w_e = *(const float4*)(we + o);
            const float4 w_o = *(const float4*)(wo + o);
            const float4 a0 = *(const float4*)(B0 + o);
            const float4 a1 = *(const float4*)(B1 + o);
            const float4 a2 = *(const float4*)(B2 + o);
            const float4 a3 = *(const float4*)(B3 + o);
            e0 = fmaf(w_e.x, a0.x, e0); e0 = fmaf(w_e.y, a0.y, e0);
            e0 = fmaf(w_e.z, a0.z, e0); e0 = fmaf(w_e.w, a0.w, e0);
            e1 = fmaf(w_e.x, a1.x, e1); e1 = fmaf(w_e.y, a1.y, e1);
            e1 = fmaf(w_e.z, a1.z, e1); e1 = fmaf(w_e.w, a1.w, e1);
            e2 = fmaf(w_e.x, a2.x, e2); e2 = fmaf(w_e.y, a2.y, e2);
            e2 = fmaf(w_e.z, a2.z, e2); e2 = fmaf(w_e.w, a2.w, e2);
            e3 = fmaf(w_e.x, a3.x, e3); e3 = fmaf(w_e.y, a3.y, e3);
            e3 = fmaf(w_e.z, a3.z, e3); e3 = fmaf(w_e.w, a3.w, e3);
            o0 = fmaf(w_o.x, a0.x, o0); o0 = fmaf(w_o.y, a0.y, o0);
            o0 = fmaf(w_o.z, a0.z, o0); o0 = fmaf(w_o.w, a0.w, o0);
            o1 = fmaf(w_o.x, a1.x, o1); o1 = fmaf(w_o.y, a1.y, o1);
            o1 = fmaf(w_o.z, a1.z, o1); o1 = fmaf(w_o.w, a1.w, o1);
            o2 = fmaf(w_o.x, a2.x, o2); o2 = fmaf(w_o.y, a2.y, o2);
            o2 = fmaf(w_o.z, a2.z, o2); o2 = fmaf(w_o.w, a2.w, o2);
            o3 = fmaf(w_o.x, a3.x, o3); o3 = fmaf(w_o.y, a3.y, o3);
            o3 = fmaf(w_o.z, a3.z, o3); o3 = fmaf(w_o.w, a3.w, o3);
        }
        __syncthreads();
    }

    // ---- stage w2 (8B cp.async) ----
    for (int u = tid; u < HID * (HID / 2); u += MLPT) {
        const int j = u / (HID / 2), s2 = u - j * (HID / 2);
        const int rm = (j >> 1) + (j & 1) * 76;
        CP8(wt_s + (unsigned)(rm * W2ROW + s2 * 2) * 4,
            w2 + (size_t)j * HID + s2 * 2);
    }
    asm volatile("cp.async.commit_group;\n" ::: "memory");

    // ---- write layer-1 partials (kh=0 -> h1s, kh=1 -> h2s) ----
    if (j0 < HID) {
        float* P = kh ? h2s : h1s;
        P[(q + 0)  * HPAD + j0]     = e0;
        P[(q + 4)  * HPAD + j0]     = e1;
        P[(q + 8)  * HPAD + j0]     = e2;
        P[(q + 12) * HPAD + j0]     = e3;
        P[(q + 0)  * HPAD + j0 + 1] = o0;
        P[(q + 4)  * HPAD + j0 + 1] = o1;
        P[(q + 8)  * HPAD + j0 + 1] = o2;
        P[(q + 12) * HPAD + j0 + 1] = o3;
    }
    __syncthreads();

    // ---- combine partials: h1 = relu(p_even + p_odd + b1) ----
    for (int idx = tid; idx < TMM * 160; idx += MLPT) {
        const int t = idx / 160, j = idx - t * 160;
        if (j < HID)
            h1s[t * HPAD + j] = fmaxf(h1s[t * HPAD + j] + h2s[t * HPAD + j]
                                      + b1[j], 0.f);
    }
    asm volatile("cp.async.wait_group 0;\n" ::: "memory");
    __syncthreads();

    // ---------------- layer 2: h2 = relu(h1 @ w2^T + b2), one j/thread ------
    {
        const int j  = tid >> 2;                 // 0..159
        const int jc = min(j, HID - 1);
        const int rm = (jc >> 1) + (jc & 1) * 76;
        const float* wr = wt + rm * W2ROW;
        const float* B0 = h1s + (q + 0)  * HPAD;
        const float* B1 = h1s + (q + 4)  * HPAD;
        const float* B2 = h1s + (q + 8)  * HPAD;
        const float* B3 = h1s + (q + 12) * HPAD;

        float c0 = 0.f, c1 = 0.f, c2 = 0.f, c3 = 0.f;
        #pragma unroll 5
        for (int p = 0; p < HID / 2; ++p) {
            const float2 wv = *(const float2*)(wr + 2 * p);
            const float2 a0 = *(const float2*)(B0 + 2 * p);
            const float2 a1 = *(const float2*)(B1 + 2 * p);
            const float2 a2 = *(const float2*)(B2 + 2 * p);
            const float2 a3 = *(const float2*)(B3 + 2 * p);
            c0 = fmaf(wv.x, a0.x, c0); c0 = fmaf(wv.y, a0.y, c0);
            c1 = fmaf(wv.x, a1.x, c1); c1 = fmaf(wv.y, a1.y, c1);
            c2 = fmaf(wv.x, a2.x, c2); c2 = fmaf(wv.y, a2.y, c2);
            c3 = fmaf(wv.x, a3.x, c3); c3 = fmaf(wv.y, a3.y, c3);
        }
        __syncthreads();                         // h1 reads done before h2s reuse
        if (j < HID) {
            const float bb = b2[j];
            h2s[(q + 0)  * HPAD + j] = fmaxf(c0 + bb, 0.f);
            h2s[(q + 4)  * HPAD + j] = fmaxf(c1 + bb, 0.f);
            h2s[(q + 8)  * HPAD + j] = fmaxf(c2 + bb, 0.f);
            h2s[(q + 12) * HPAD + j] = fmaxf(c3 + bb, 0.f);
        }
    }
    __syncthreads();

    // ---------------- layer 3: attns = h2 @ w3^T + b3 -----------------------
    {
        const int wrp  = tid >> 5;
        const int lane = tid & 31;
        if (wrp < TMM) {
            float acc = 0.f;
            #pragma unroll
            for (int i = 0; i < 5; ++i) {
                const int kk = lane + 32 * i;
                if (kk < HID) acc += w3[kk] * h2s[wrp * HPAD + kk];
            }
            #pragma unroll
            for (int off = 16; off; off >>= 1)
                acc += __shfl_xor_sync(0xffffffffu, acc, off);
            if (lane == 0) g_attns[t0 + wrp] = acc + b3[0];
        }
    }
}

// ---------------------------------------------------------------------------
// Kernel 2: span assembly (unchanged — pinned at the HBM write floor)
// ---------------------------------------------------------------------------
__global__ __launch_bounds__(256) void assemble_kernel(
    const float* __restrict__ embeds,
    const float* __restrict__ states,
    float* __restrict__ out)
{
    const int r    = blockIdx.x;
    const int tid  = threadIdx.x;
    const int nmax = min(MAXW, T_TOK - r);

    __shared__ __align__(16) float se[MAXW][EDIM];
    __shared__ float ws[MAXW];
    __shared__ float invden[MAXW];

    {
        unsigned smem_addr = (unsigned)__cvta_generic_to_shared(&se[0][tid * 4]);
        const float4* src = (const float4*)embeds + (size_t)r * 256 + tid;
        #pragma unroll
        for (int i = 0; i < MAXW; i++) {
            if (i < nmax) {
                asm volatile("cp.async.cg.shared.global [%0], [%1], 16;\n"
                             :: "r"(smem_addr + i * (EDIM * 4)), "l"(src + i * 256));
            }
        }
        asm volatile("cp.async.commit_group;\n" ::: "memory");
    }

    if (tid == 0) {
        float a[MAXW];
        float m = -1e30f;
        for (int i = 0; i < nmax; i++) {
            a[i] = g_attns[r + i];
            m = fmaxf(m, a[i]);
        }
        float den = 0.f;
        for (int i = 0; i < nmax; i++) {
            float e = __expf(a[i] - m);
            ws[i] = e;
            den += e;
            invden[i] = 1.0f / den;
        }
    }
    asm volatile("cp.async.wait_group 0;\n" ::: "memory");
    __syncthreads();

    const float4* st4  = (const float4*)states;
    float4*       out4 = (float4*)out;

    const float4 s0 = st4[r * 256 + tid];
    float4 num = make_float4(0.f, 0.f, 0.f, 0.f);

    #pragma unroll
    for (int i = 0; i < MAXW; i++) {
        if (i < nmax) {
            const float  wv = ws[i];
            const float4 e  = ((const float4*)se[i])[tid];
            num.x += wv * e.x; num.y += wv * e.y;
            num.z += wv * e.z; num.w += wv * e.w;

            const int row  = i * (T_TOK + 1) - ((i + 1) * i) / 2 + r;
            const int base = row * 768;

            const float4 send = st4[(r + i) * 256 + tid];
            const float  id   = invden[i];
            __stcs(&out4[base + tid],       s0);
            __stcs(&out4[base + 256 + tid], send);
            __stcs(&out4[base + 512 + tid],
                   make_float4(num.x * id, num.y * id, num.z * id, num.w * id));
        }
    }
}

// ---------------------------------------------------------------------------
extern "C" void kernel_launch(void* const* d_in, const int* in_sizes, int n_in,
                              void* d_out, int out_size) {
    const float* embeds = (const float*)d_in[0];
    const float* states = (const float*)d_in[1];
    const float* w1     = (const float*)d_in[2];
    const float* b1     = (const float*)d_in[3];
    const float* w2     = (const float*)d_in[4];
    const float* b2     = (const float*)d_in[5];
    const float* w3     = (const float*)d_in[6];
    const float* b3     = (const float*)d_in[7];
    float* out = (float*)d_out;

    mlp_kernel<<<T_TOK / TMM, MLPT>>>(states, w1, b1, w2, b2, w3, b3);
    assemble_kernel<<<T_TOK, 256>>>(embeds, states, out);
}

// round 12
// speedup vs baseline: 1.3671x; 1.0382x over previous
#include <cuda_runtime.h>

#define T_TOK 2048
#define SDIM  1024
#define EDIM  1024
#define HID   150
#define MAXW  10

#define TMM    16             // tokens per MLP block
#define MLPT   640            // MLP threads (20 warps = 5/SMSP)
#define KPAD   1032           // As row stride (floats)
#define HPAD   158            // h row stride (floats)
#define WROW   88             // w1 tile row stride (floats)
#define W2ROW  156            // w2 tile row stride (floats)
#define KC     64             // K-chunk (floats)
#define CHUNKS 16             // 1024 / 64
#define WTILE  (160 * WROW)   // floats per w1 buffer (14080)

#define SMEM_FLOATS (TMM*KPAD + 2*WTILE + 2*TMM*HPAD)   // ~199 KB

__device__ float g_attns[T_TOK];

#define CP16(dst_s, src_g) \
    asm volatile("cp.async.cg.shared.global [%0], [%1], 16;\n" :: "r"(dst_s), "l"(src_g))
#define CP8(dst_s, src_g) \
    asm volatile("cp.async.ca.shared.global [%0], [%1], 8;\n" :: "r"(dst_s), "l"(src_g))

// ---------------------------------------------------------------------------
// Kernel 1: fused 3-layer MLP (per-token score) + states-copy output sections.
// MLP structure identical to R11 (best). Additionally, each block streams the
// start-state and end-state output sections for its 16 tokens (16 x 80 KB),
// interleaved into the layer-1 chunk loop: 8 LDS.128+STG.128 per thread per
// chunk. The copy is write-BW work that overlaps the issue-bound MLP compute.
// ---------------------------------------------------------------------------
__global__ __launch_bounds__(MLPT) void mlp_copy_kernel(
    const float* __restrict__ states,
    const float* __restrict__ w1, const float* __restrict__ b1,
    const float* __restrict__ w2, const float* __restrict__ b2,
    const float* __restrict__ w3, const float* __restrict__ b3,
    float* __restrict__ out)
{
    __shared__ __align__(16) float sm[SMEM_FLOATS];
    float* As  = sm;                    // [16][KPAD]
    float* wt  = As + TMM * KPAD;       // [2][WTILE] (later aliased by w2)
    float* h1s = wt + 2 * WTILE;        // [16][HPAD] (kh=0 partials -> h1)
    float* h2s = h1s + TMM * HPAD;      // [16][HPAD] (kh=1 partials -> h2)

    const int tid = threadIdx.x;
    const int t0  = blockIdx.x * TMM;
    float4* out4  = (float4*)out;

    const unsigned wt_s = (unsigned)__cvta_generic_to_shared(wt);

    // ---- stage w1 chunk 0 ----
    for (int u = tid; u < HID * 16; u += MLPT) {
        const int j = u >> 4, seg = u & 15;
        const int rm = (j >> 1) + (j & 1) * 80;
        CP16(wt_s + (unsigned)(rm * WROW + seg * 4) * 4,
             w1 + (size_t)j * SDIM + seg * 4);
    }
    asm volatile("cp.async.commit_group;\n" ::: "memory");

    // ---- stage 16 token states ----
    for (int idx = tid; idx < TMM * (SDIM / 4); idx += MLPT) {
        const int t = idx >> 8, k4 = idx & 255;
        const float4 v = ((const float4*)states)[(size_t)(t0 + t) * 256 + k4];
        *(float4*)&As[t * KPAD + k4 * 4] = v;
    }

    const int q  = tid & 3;
    const int kh = (tid >> 2) & 1;
    const int jp = tid >> 3;
    const int j0 = 2 * jp;
    const int re = min(jp, 74);
    const int ro = 80 + re;

    const float* A0 = As + (q + 0)  * KPAD;
    const float* A1 = As + (q + 4)  * KPAD;
    const float* A2 = As + (q + 8)  * KPAD;
    const float* A3 = As + (q + 12) * KPAD;

    // ---------------- layer 1 + interleaved copy stores ---------------------
    float e0 = 0.f, e1 = 0.f, e2 = 0.f, e3 = 0.f;
    float o0 = 0.f, o1 = 0.f, o2 = 0.f, o3 = 0.f;

    for (int c = 0; c < CHUNKS; ++c) {
        if (c + 1 < CHUNKS) {
            const int nb = (c + 1) & 1;
            for (int u = tid; u < HID * 16; u += MLPT) {
                const int j = u >> 4, seg = u & 15;
                const int rm = (j >> 1) + (j & 1) * 80;
                CP16(wt_s + (unsigned)(nb * WTILE + rm * WROW + seg * 4) * 4,
                     w1 + (size_t)j * SDIM + (c + 1) * KC + seg * 4);
            }
            asm volatile("cp.async.commit_group;\n" ::: "memory");
            asm volatile("cp.async.wait_group 1;\n" ::: "memory");
        } else {
            asm volatile("cp.async.wait_group 0;\n" ::: "memory");
        }
        __syncthreads();

        const float* wb = wt + (c & 1) * WTILE;
        const float* we = wb + re * WROW + kh * 4;
        const float* wo = wb + ro * WROW + kh * 4;
        const float* B0 = A0 + c * KC + kh * 4;
        const float* B1 = A1 + c * KC + kh * 4;
        const float* B2 = A2 + c * KC + kh * 4;
        const float* B3 = A3 + c * KC + kh * 4;

        #pragma unroll
        for (int i = 0; i < 8; ++i) {
            const int o = i * 8;
            const float4 w_e = *(const float4*)(we + o);
            const float4 w_o = *(const float4*)(wo + o);
            const float4 a0 = *(const float4*)(B0 + o);
            const float4 a1 = *(const float4*)(B1 + o);
            const float4 a2 = *(const float4*)(B2 + o);
            const float4 a3 = *(const float4*)(B3 + o);
            e0 = fmaf(w_e.x, a0.x, e0); e0 = fmaf(w_e.y, a0.y, e0);
            e0 = fmaf(w_e.z, a0.z, e0); e0 = fmaf(w_e.w, a0.w, e0);
            e1 = fmaf(w_e.x, a1.x, e1); e1 = fmaf(w_e.y, a1.y, e1);
            e1 = fmaf(w_e.z, a1.z, e1); e1 = fmaf(w_e.w, a1.w, e1);
            e2 = fmaf(w_e.x, a2.x, e2); e2 = fmaf(w_e.y, a2.y, e2);
            e2 = fmaf(w_e.z, a2.z, e2); e2 = fmaf(w_e.w, a2.w, e2);
            e3 = fmaf(w_e.x, a3.x, e3); e3 = fmaf(w_e.y, a3.y, e3);
            e3 = fmaf(w_e.z, a3.z, e3); e3 = fmaf(w_e.w, a3.w, e3);
            o0 = fmaf(w_o.x, a0.x, o0); o0 = fmaf(w_o.y, a0.y, o0);
            o0 = fmaf(w_o.z, a0.z, o0); o0 = fmaf(w_o.w, a0.w, o0);
            o1 = fmaf(w_o.x, a1.x, o1); o1 = fmaf(w_o.y, a1.y, o1);
            o1 = fmaf(w_o.z, a1.z, o1); o1 = fmaf(w_o.w, a1.w, o1);
            o2 = fmaf(w_o.x, a2.x, o2); o2 = fmaf(w_o.y, a2.y, o2);
            o2 = fmaf(w_o.z, a2.z, o2); o2 = fmaf(w_o.w, a2.w, o2);
            o3 = fmaf(w_o.x, a3.x, o3); o3 = fmaf(w_o.y, a3.y, o3);
            o3 = fmaf(w_o.z, a3.z, o3); o3 = fmaf(w_o.w, a3.w, o3);
        }

        // ---- copy stores: 8 items/thread/chunk; item = (sec, token, f4) ----
        // sec 0..9  = start-state section (width i+1), row(i, r)
        // sec 10..19= end-state section,   row(i, r-i) + 256-offset
        #pragma unroll
        for (int it = 0; it < 8; ++it) {
            const int g    = (c * 8 + it) * MLPT + tid;   // 0..81919
            const int f4   = g & 255;
            const int rest = g >> 8;                      // 0..319
            const int th   = rest & 15;
            const int sec  = rest >> 4;                   // 0..19
            const int wi   = (sec < 10) ? sec : sec - 10;
            const int r    = t0 + th;
            const float4 v = *(const float4*)&As[th * KPAD + f4 * 4];
            const int tri  = wi * (T_TOK + 1) - ((wi + 1) * wi) / 2;
            if (sec < 10) {
                if (r + wi < T_TOK)
                    __stcs(&out4[(tri + r) * 768 + f4], v);
            } else {
                if (r - wi >= 0)
                    __stcs(&out4[(tri + r - wi) * 768 + 256 + f4], v);
            }
        }
        __syncthreads();
    }

    // ---- stage w2 ----
    for (int u = tid; u < HID * (HID / 2); u += MLPT) {
        const int j = u / (HID / 2), s2 = u - j * (HID / 2);
        const int rm = (j >> 1) + (j & 1) * 76;
        CP8(wt_s + (unsigned)(rm * W2ROW + s2 * 2) * 4,
            w2 + (size_t)j * HID + s2 * 2);
    }
    asm volatile("cp.async.commit_group;\n" ::: "memory");

    // ---- write layer-1 partials ----
    if (j0 < HID) {
        float* P = kh ? h2s : h1s;
        P[(q + 0)  * HPAD + j0]     = e0;
        P[(q + 4)  * HPAD + j0]     = e1;
        P[(q + 8)  * HPAD + j0]     = e2;
        P[(q + 12) * HPAD + j0]     = e3;
        P[(q + 0)  * HPAD + j0 + 1] = o0;
        P[(q + 4)  * HPAD + j0 + 1] = o1;
        P[(q + 8)  * HPAD + j0 + 1] = o2;
        P[(q + 12) * HPAD + j0 + 1] = o3;
    }
    __syncthreads();

    // ---- combine partials: h1 = relu(p_even + p_odd + b1) ----
    for (int idx = tid; idx < TMM * 160; idx += MLPT) {
        const int t = idx / 160, j = idx - t * 160;
        if (j < HID)
            h1s[t * HPAD + j] = fmaxf(h1s[t * HPAD + j] + h2s[t * HPAD + j]
                                      + b1[j], 0.f);
    }
    asm volatile("cp.async.wait_group 0;\n" ::: "memory");
    __syncthreads();

    // ---------------- layer 2 ----------------
    {
        const int j  = tid >> 2;
        const int jc = min(j, HID - 1);
        const int rm = (jc >> 1) + (jc & 1) * 76;
        const float* wr = wt + rm * W2ROW;
        const float* B0 = h1s + (q + 0)  * HPAD;
        const float* B1 = h1s + (q + 4)  * HPAD;
        const float* B2 = h1s + (q + 8)  * HPAD;
        const float* B3 = h1s + (q + 12) * HPAD;

        float c0 = 0.f, c1 = 0.f, c2 = 0.f, c3 = 0.f;
        #pragma unroll 5
        for (int p = 0; p < HID / 2; ++p) {
            const float2 wv = *(const float2*)(wr + 2 * p);
            const float2 a0 = *(const float2*)(B0 + 2 * p);
            const float2 a1 = *(const float2*)(B1 + 2 * p);
            const float2 a2 = *(const float2*)(B2 + 2 * p);
            const float2 a3 = *(const float2*)(B3 + 2 * p);
            c0 = fmaf(wv.x, a0.x, c0); c0 = fmaf(wv.y, a0.y, c0);
            c1 = fmaf(wv.x, a1.x, c1); c1 = fmaf(wv.y, a1.y, c1);
            c2 = fmaf(wv.x, a2.x, c2); c2 = fmaf(wv.y, a2.y, c2);
            c3 = fmaf(wv.x, a3.x, c3); c3 = fmaf(wv.y, a3.y, c3);
        }
        __syncthreads();
        if (j < HID) {
            const float bb = b2[j];
            h2s[(q + 0)  * HPAD + j] = fmaxf(c0 + bb, 0.f);
            h2s[(q + 4)  * HPAD + j] = fmaxf(c1 + bb, 0.f);
            h2s[(q + 8)  * HPAD + j] = fmaxf(c2 + bb, 0.f);
            h2s[(q + 12) * HPAD + j] = fmaxf(c3 + bb, 0.f);
        }
    }
    __syncthreads();

    // ---------------- layer 3 ----------------
    {
        const int wrp  = tid >> 5;
        const int lane = tid & 31;
        if (wrp < TMM) {
            float acc = 0.f;
            #pragma unroll
            for (int i = 0; i < 5; ++i) {
                const int kk = lane + 32 * i;
                if (kk < HID) acc += w3[kk] * h2s[wrp * HPAD + kk];
            }
            #pragma unroll
            for (int off = 16; off; off >>= 1)
                acc += __shfl_xor_sync(0xffffffffu, acc, off);
            if (lane == 0) g_attns[t0 + wrp] = acc + b3[0];
        }
    }
}

// ---------------------------------------------------------------------------
// Kernel 2: pooled-only assembly. One block per start r; running-softmax
// numerator over widths 1..10; writes ONLY the pooled-embed third.
// ---------------------------------------------------------------------------
__global__ __launch_bounds__(256) void pooled_kernel(
    const float* __restrict__ embeds,
    float* __restrict__ out)
{
    const int r    = blockIdx.x;
    const int tid  = threadIdx.x;
    const int nmax = min(MAXW, T_TOK - r);

    __shared__ __align__(16) float se[MAXW][EDIM];
    __shared__ float ws[MAXW];
    __shared__ float invden[MAXW];

    {
        unsigned smem_addr = (unsigned)__cvta_generic_to_shared(&se[0][tid * 4]);
        const float4* src = (const float4*)embeds + (size_t)r * 256 + tid;
        #pragma unroll
        for (int i = 0; i < MAXW; i++) {
            if (i < nmax) {
                asm volatile("cp.async.cg.shared.global [%0], [%1], 16;\n"
                             :: "r"(smem_addr + i * (EDIM * 4)), "l"(src + i * 256));
            }
        }
        asm volatile("cp.async.commit_group;\n" ::: "memory");
    }

    if (tid == 0) {
        float a[MAXW];
        float m = -1e30f;
        for (int i = 0; i < nmax; i++) {
            a[i] = g_attns[r + i];
            m = fmaxf(m, a[i]);
        }
        float den = 0.f;
        for (int i = 0; i < nmax; i++) {
            float e = __expf(a[i] - m);
            ws[i] = e;
            den += e;
            invden[i] = 1.0f / den;
        }
    }
    asm volatile("cp.async.wait_group 0;\n" ::: "memory");
    __syncthreads();

    float4* out4 = (float4*)out;
    float4 num = make_float4(0.f, 0.f, 0.f, 0.f);

    #pragma unroll
    for (int i = 0; i < MAXW; i++) {
        if (i < nmax) {
            const float  wv = ws[i];
            const float4 e  = ((const float4*)se[i])[tid];
            num.x += wv * e.x; num.y += wv * e.y;
            num.z += wv * e.z; num.w += wv * e.w;

            const int row = i * (T_TOK + 1) - ((i + 1) * i) / 2 + r;
            const float id = invden[i];
            __stcs(&out4[row * 768 + 512 + tid],
                   make_float4(num.x * id, num.y * id, num.z * id, num.w * id));
        }
    }
}

// ---------------------------------------------------------------------------
extern "C" void kernel_launch(void* const* d_in, const int* in_sizes, int n_in,
                              void* d_out, int out_size) {
    const float* embeds = (const float*)d_in[0];
    const float* states = (const float*)d_in[1];
    const float* w1     = (const float*)d_in[2];
    const float* b1     = (const float*)d_in[3];
    const float* w2     = (const float*)d_in[4];
    const float* b2     = (const float*)d_in[5];
    const float* w3     = (const float*)d_in[6];
    const float* b3     = (const float*)d_in[7];
    float* out = (float*)d_out;

    mlp_copy_kernel<<<T_TOK / TMM, MLPT>>>(states, w1, b1, w2, b2, w3, b3, out);
    pooled_kernel<<<T_TOK, 256>>>(embeds, out);
}